// round 10
// baseline (speedup 1.0000x reference)
#include <cuda_runtime.h>
#include <math.h>
#include <cstdint>

#define BSZ  16      // batch
#define NCAP 1152    // primary caps
#define DP   8       // dim primary
#define DDIG 10      // digit caps
#define DD   16      // dim digit

#define TILE_N 16
#define NT (NCAP / TILE_N)   // 72

#define K2TN 4               // n-tile in k2
#define K2CTAS (NCAP / K2TN) // 288

// Scratch (device globals; zero-init at load; invariants restored every call)
__device__ __align__(16) float g_T[BSZ * DDIG * DD];   // T (k1 atomics; re-zeroed by k2)
__device__ __align__(16) float g_S[BSZ * DDIG * DD];   // S (k2 atomics; re-zeroed by k2)
__device__ unsigned int g_cnt;                          // self-resetting wrap counter

// -------------------------------------------------------------------------
// K1: T[b,d,j] = sum_n W[d,n,j,:]·u[b,n,:]   (no U_hat materialization)
// Grid (DDIG, NT) = 720 CTAs x 256 threads.
// -------------------------------------------------------------------------
__global__ __launch_bounds__(256) void k1_votes(
    const float* __restrict__ u,   // [B][N][DP]
    const float* __restrict__ W)   // [D][N][DD][DP]
{
    const int d    = blockIdx.x;
    const int tile = blockIdx.y;
    const int n0   = tile * TILE_N;
    const int t    = threadIdx.x;
    const int j    = t & 15;
    const int nl   = t >> 4;
    const int n    = n0 + nl;
    const int lane = t & 31;
    const int w    = t >> 5;

    const float4* wp = reinterpret_cast<const float4*>(
        W + ((size_t)(d * NCAP + n) * DD + j) * DP);
    const float4 w0 = wp[0];
    const float4 w1 = wp[1];

    __shared__ __align__(16) float us[BSZ][TILE_N][DP];   // 8 KB
    __shared__ float red[BSZ][8][DD];                     // 8 KB

    #pragma unroll
    for (int it = 0; it < 2; ++it) {
        const int idx = it * 256 + t;
        const int b   = idx >> 5;
        const int rem = idx & 31;
        const float4 v = reinterpret_cast<const float4*>(
            u + (size_t)b * NCAP * DP + (size_t)n0 * DP)[rem];
        reinterpret_cast<float4*>(&us[b][0][0])[rem] = v;
    }
    __syncthreads();

    #pragma unroll
    for (int b = 0; b < BSZ; ++b) {
        const float4* up = reinterpret_cast<const float4*>(&us[b][nl][0]);
        const float4 u0 = up[0];
        const float4 u1 = up[1];
        const float acc = w0.x * u0.x + w0.y * u0.y + w0.z * u0.z + w0.w * u0.w
                        + w1.x * u1.x + w1.y * u1.y + w1.z * u1.z + w1.w * u1.w;
        const float ps = acc + __shfl_xor_sync(0xffffffffu, acc, 16);
        if (lane < 16) red[b][w][lane] = ps;
    }
    __syncthreads();

    {
        const int b2 = t >> 4;
        const int j2 = t & 15;
        float s = 0.f;
        #pragma unroll
        for (int ww = 0; ww < 8; ++ww) s += red[b2][ww][j2];
        atomicAdd(&g_T[(b2 * DDIG + d) * DD + j2], s);
    }
}

// -------------------------------------------------------------------------
// K2: recompute pass. CTA per 4-n tile; threads (16 b x 16 j).
// Per n: uh[d] recomputed from SMEM W-tile, a[d] via j-shfl-reduce with T,
// softmax over d in registers, S accumulated locally then RED.ADD to g_S.
// Last CTA (fence + wrap counter) squashes all b and resets g_S/g_T.
// -------------------------------------------------------------------------
__global__ __launch_bounds__(256) void k2_rest(
    const float* __restrict__ u,   // [B][N][DP]
    const float* __restrict__ W,   // [D][N][DD][DP]
    const float* __restrict__ Bp,  // [D][1][N]
    float* __restrict__ out)       // [B][D][DD]
{
    const int nc = blockIdx.x;       // 0..287
    const int n0 = nc * K2TN;
    const int t  = threadIdx.x;

    __shared__ __align__(16) float Ws[K2TN][DDIG][DD * DP];  // 20 KB [nl][d][j*8+i]
    __shared__ __align__(16) float Ts[BSZ * DDIG * DD];      // 10 KB
    __shared__ __align__(16) float us[BSZ][K2TN][DP];        // 2 KB
    __shared__ float Bps[DDIG][K2TN];
    __shared__ __align__(16) float Ssm[BSZ * DDIG * DD];     // 10 KB (finalize)
    __shared__ float coef[BSZ * DDIG];
    __shared__ unsigned int is_last;

    // ---- stage W tile: 5120 floats = 1280 float4, 5 per thread ----
    #pragma unroll
    for (int k = 0; k < 5; ++k) {
        const int idx    = k * 256 + t;      // 0..1279
        const int blk    = idx >> 5;         // 40 blocks of 32 f4
        const int within = idx & 31;
        const int d  = blk >> 2;
        const int nl = blk & 3;
        const float4 v = reinterpret_cast<const float4*>(W)[
            (size_t)(d * NCAP + n0 + nl) * 32 + within];
        reinterpret_cast<float4*>(&Ws[nl][d][0])[within] = v;
    }
    // ---- stage T: 2560 floats = 640 float4 ----
    #pragma unroll
    for (int k = 0; k < 3; ++k) {
        const int idx = k * 256 + t;
        if (idx < BSZ * DDIG * DD / 4)
            reinterpret_cast<float4*>(Ts)[idx] =
                reinterpret_cast<const float4*>(g_T)[idx];
    }
    // ---- stage u: 512 floats = 128 float4 ----
    if (t < 128) {
        const int b = t >> 3;
        const int q = t & 7;
        reinterpret_cast<float4*>(&us[b][0][0])[q] =
            reinterpret_cast<const float4*>(u)[(size_t)(b * NCAP + n0) * 2 + q];
    }
    // ---- stage Bp tile ----
    if (t < DDIG * K2TN)
        Bps[t >> 2][t & 3] = Bp[(size_t)(t >> 2) * NCAP + n0 + (t & 3)];
    __syncthreads();

    const int b = t >> 4;
    const int j = t & 15;
    const float inv_sqrt8 = 0.3535533905932738f;

    float Sloc[DDIG];
    #pragma unroll
    for (int d = 0; d < DDIG; ++d) Sloc[d] = 0.f;

    #pragma unroll
    for (int nl = 0; nl < K2TN; ++nl) {
        const float4* up = reinterpret_cast<const float4*>(&us[b][nl][0]);
        const float4 u0 = up[0];
        const float4 u1 = up[1];

        float uh[DDIG];
        #pragma unroll
        for (int d = 0; d < DDIG; ++d) {
            const float4* wq = reinterpret_cast<const float4*>(&Ws[nl][d][j * DP]);
            const float4 wa = wq[0];
            const float4 wb = wq[1];
            uh[d] = wa.x * u0.x + wa.y * u0.y + wa.z * u0.z + wa.w * u0.w
                  + wb.x * u1.x + wb.y * u1.y + wb.z * u1.z + wb.w * u1.w;
        }

        float a[DDIG];
        #pragma unroll
        for (int d = 0; d < DDIG; ++d) {
            float p = Ts[(b * DDIG + d) * DD + j] * uh[d];
            p += __shfl_xor_sync(0xffffffffu, p, 1);
            p += __shfl_xor_sync(0xffffffffu, p, 2);
            p += __shfl_xor_sync(0xffffffffu, p, 4);
            p += __shfl_xor_sync(0xffffffffu, p, 8);
            a[d] = p * inv_sqrt8;
        }

        float m = a[0];
        #pragma unroll
        for (int d = 1; d < DDIG; ++d) m = fmaxf(m, a[d]);
        float denom = 0.f;
        #pragma unroll
        for (int d = 0; d < DDIG; ++d) { a[d] = __expf(a[d] - m); denom += a[d]; }
        const float rden = 1.f / denom;

        #pragma unroll
        for (int d = 0; d < DDIG; ++d) {
            const float wg = a[d] * rden + Bps[d][nl];
            Sloc[d] += wg * uh[d];
        }
    }

    // spread-address RED.ADD: one per (b,d,j) — no intra-CTA contention
    #pragma unroll
    for (int d = 0; d < DDIG; ++d)
        atomicAdd(&g_S[(b * DDIG + d) * DD + j], Sloc[d]);

    // ---- last-CTA finalize ----
    __threadfence();
    __syncthreads();
    if (t == 0)
        is_last = (atomicInc(&g_cnt, K2CTAS - 1) == K2CTAS - 1) ? 1u : 0u;
    __syncthreads();
    if (!is_last) return;

    for (int idx = t; idx < BSZ * DDIG * DD; idx += 256) {
        Ssm[idx] = __ldcg(&g_S[idx]);   // L2-fresh
        g_S[idx] = 0.f;                 // restore invariants for next call
        g_T[idx] = 0.f;
    }
    __syncthreads();
    if (t < BSZ * DDIG) {               // t = b*10+d
        float nn = 0.f;
        #pragma unroll
        for (int jj = 0; jj < DD; ++jj) {
            const float v = Ssm[t * DD + jj];
            nn += v * v;
        }
        const float norm = sqrtf(nn);
        const float EPS  = 1e-7f;
        coef[t] = (1.f - 1.f / (__expf(norm) + EPS)) / (norm + EPS);
    }
    __syncthreads();
    for (int idx = t; idx < BSZ * DDIG * DD; idx += 256)
        out[idx] = coef[idx >> 4] * Ssm[idx];
}

// -------------------------------------------------------------------------
extern "C" void kernel_launch(void* const* d_in, const int* in_sizes, int n_in,
                              void* d_out, int out_size)
{
    const float* u  = (const float*)d_in[0];   // primary_caps [16,1152,8]
    const float* W  = (const float*)d_in[1];   // W            [10,1152,16,8]
    const float* Bp = (const float*)d_in[2];   // B_prior      [10,1,1152]
    float* out      = (float*)d_out;           // [16,10,16]

    (void)in_sizes; (void)n_in; (void)out_size;

    k1_votes<<<dim3(DDIG, NT), 256>>>(u, W);
    k2_rest <<<K2CTAS, 256>>>(u, W, Bp, out);
}